// round 2
// baseline (speedup 1.0000x reference)
#include <cuda_runtime.h>
#include <cuda_bf16.h>
#include <cstdint>

#define MAX_NODES 100000
#define FEAT 128

// ---------------- scratch (no allocation allowed) ----------------
__device__ float g_hs [MAX_NODES * FEAT];   // h * dinv[row]  (gather source)
__device__ float g_agg[MAX_NODES * FEAT];   // accumulator (init = self-loop term)
__device__ float g_buf[MAX_NODES * FEAT];   // layer output / next layer input
__device__ float g_dinv[MAX_NODES];
__device__ int   g_deg [MAX_NODES];

// ---------------- degree / dinv ----------------
__global__ void deg_init_kernel(int* deg, int M) {
    int i = blockIdx.x * blockDim.x + threadIdx.x;
    if (i < M) deg[i] = 1;                      // self-loop
}
__global__ void deg_acc_kernel(int* deg, const int* __restrict__ dst, int E) {
    int e = blockIdx.x * blockDim.x + threadIdx.x;
    if (e < E) atomicAdd(&deg[dst[e]], 1);
}
__global__ void dinv_kernel(float* dinv, const int* __restrict__ deg, int M) {
    int i = blockIdx.x * blockDim.x + threadIdx.x;
    if (i < M) dinv[i] = rsqrtf((float)deg[i]);
}

// ---------------- GEMM: hs = (A @ W) * dinv[row]; agg = hs ----------------
// A: [M, 128] row-major. W: [128, N] row-major. N in {128, 64}.
// Block: 256 threads computes 64 rows x N cols. K chunked by 32.
template <int N>
__global__ __launch_bounds__(256)
void gemm_kernel(const float* __restrict__ A, const float* __restrict__ W,
                 const float* __restrict__ dinv,
                 float* __restrict__ hs, float* __restrict__ agg, int M)
{
    constexpr int K  = 128;
    constexpr int TM = 64;
    constexpr int KC = 32;
    constexpr int CN = N / 32;                  // cols per thread: 4 or 2

    __shared__ __align__(16) float As[TM][KC];  // 8 KB
    __shared__ __align__(16) float Ws[KC][N];   // 16 KB (N=128) / 8 KB (N=64)

    const int tid  = threadIdx.x;
    const int tx   = tid & 31;                  // 0..31 -> col group
    const int ty   = tid >> 5;                  // 0..7  -> row group
    const int row0 = blockIdx.x * TM;

    float acc[8][CN];
#pragma unroll
    for (int i = 0; i < 8; i++)
#pragma unroll
        for (int c = 0; c < CN; c++) acc[i][c] = 0.f;

    for (int k0 = 0; k0 < K; k0 += KC) {
        // load A chunk: TM x KC floats (2 float4 per thread), guarded
#pragma unroll
        for (int it = 0; it < (TM * KC) / (256 * 4); it++) {
            int idx = (it * 256 + tid) * 4;
            int r = idx / KC, c = idx % KC;
            float4 v = make_float4(0.f, 0.f, 0.f, 0.f);
            int grow = row0 + r;
            if (grow < M)
                v = *(const float4*)(A + (size_t)grow * K + k0 + c);
            *(float4*)&As[r][c] = v;
        }
        // load W chunk: KC x N floats
#pragma unroll
        for (int it = 0; it < (KC * N) / (256 * 4); it++) {
            int idx = (it * 256 + tid) * 4;
            int r = idx / N, c = idx % N;
            *(float4*)&Ws[r][c] = *(const float4*)(W + (size_t)(k0 + r) * N + c);
        }
        __syncthreads();

#pragma unroll
        for (int k4 = 0; k4 < KC / 4; k4++) {
            float4 a4[8];
#pragma unroll
            for (int i = 0; i < 8; i++)
                a4[i] = *(const float4*)&As[ty + 8 * i][k4 * 4];
#pragma unroll
            for (int kk = 0; kk < 4; kk++) {
                float w[CN];
                if constexpr (CN == 4) {
                    float4 w4 = *(const float4*)&Ws[k4 * 4 + kk][tx * 4];
                    w[0] = w4.x; w[1] = w4.y; w[2] = w4.z; w[3] = w4.w;
                } else {
                    float2 w2 = *(const float2*)&Ws[k4 * 4 + kk][tx * 2];
                    w[0] = w2.x; w[1] = w2.y;
                }
#pragma unroll
                for (int i = 0; i < 8; i++) {
                    float a = (kk == 0) ? a4[i].x : (kk == 1) ? a4[i].y
                             : (kk == 2) ? a4[i].z : a4[i].w;
#pragma unroll
                    for (int c = 0; c < CN; c++) acc[i][c] += a * w[c];
                }
            }
        }
        __syncthreads();
    }

    // epilogue: scale by dinv[row], write to hs and agg (self-loop init)
#pragma unroll
    for (int i = 0; i < 8; i++) {
        int grow = row0 + ty + 8 * i;
        if (grow >= M) continue;
        float di = dinv[grow];
        size_t base = (size_t)grow * N + tx * CN;
        if constexpr (CN == 4) {
            float4 v = make_float4(acc[i][0] * di, acc[i][1] * di,
                                   acc[i][2] * di, acc[i][3] * di);
            *(float4*)(hs  + base) = v;
            *(float4*)(agg + base) = v;
        } else {
            float2 v = make_float2(acc[i][0] * di, acc[i][1] * di);
            *(float2*)(hs  + base) = v;
            *(float2*)(agg + base) = v;
        }
    }
}

// ---------------- edge scatter: agg[dst] += hs[src] ----------------
template <int N>
__global__ __launch_bounds__(256)
void scatter_kernel(const int* __restrict__ src, const int* __restrict__ dst,
                    const float* __restrict__ hs, float* __restrict__ agg, int E)
{
    constexpr int CH = N / 4;                   // float4 chunks per row
    int tid = blockIdx.x * blockDim.x + threadIdx.x;
    int eid = tid / CH;
    int j   = tid % CH;
    if (eid >= E) return;
    int s = __ldg(src + eid);
    int d = __ldg(dst + eid);
    float4 v = __ldg((const float4*)(hs + (size_t)s * N) + j);
    float* p = agg + (size_t)d * N + j * 4;
    asm volatile("red.global.add.v4.f32 [%0], {%1,%2,%3,%4};"
                 :: "l"(p), "f"(v.x), "f"(v.y), "f"(v.z), "f"(v.w) : "memory");
}

// ---------------- finalize: out = agg * dinv[row] + b  (opt ReLU) ----------------
template <int N, bool RELU>
__global__ __launch_bounds__(256)
void finalize_kernel(const float* __restrict__ agg, const float* __restrict__ b,
                     const float* __restrict__ dinv, float* __restrict__ out, int M)
{
    constexpr int CH = N / 4;
    int tid = blockIdx.x * blockDim.x + threadIdx.x;
    if (tid >= M * CH) return;
    int row = tid / CH;
    int j   = tid % CH;
    float di = dinv[row];
    float4 v  = *((const float4*)agg + tid);
    float4 bb = __ldg((const float4*)b + j);
    float4 r;
    r.x = v.x * di + bb.x;
    r.y = v.y * di + bb.y;
    r.z = v.z * di + bb.z;
    r.w = v.w * di + bb.w;
    if (RELU) {
        r.x = fmaxf(r.x, 0.f); r.y = fmaxf(r.y, 0.f);
        r.z = fmaxf(r.z, 0.f); r.w = fmaxf(r.w, 0.f);
    }
    ((float4*)out)[tid] = r;
}

// ---------------- launch ----------------
extern "C" void kernel_launch(void* const* d_in, const int* in_sizes, int n_in,
                              void* d_out, int out_size)
{
    const float* x  = (const float*)d_in[0];
    const int*   ei = (const int*)  d_in[1];
    const float* W1 = (const float*)d_in[2];
    const float* b1 = (const float*)d_in[3];
    const float* W2 = (const float*)d_in[4];
    const float* b2 = (const float*)d_in[5];
    const float* W3 = (const float*)d_in[6];
    const float* b3 = (const float*)d_in[7];

    const int M = in_sizes[0] / FEAT;     // 100000
    const int E = in_sizes[1] / 2;        // 800000
    const int* src = ei;
    const int* dst = ei + E;

    float *hs, *agg, *buf, *dinv; int* deg;
    cudaGetSymbolAddress((void**)&hs,   g_hs);
    cudaGetSymbolAddress((void**)&agg,  g_agg);
    cudaGetSymbolAddress((void**)&buf,  g_buf);
    cudaGetSymbolAddress((void**)&dinv, g_dinv);
    cudaGetSymbolAddress((void**)&deg,  g_deg);

    // degrees + dinv (shared across layers)
    deg_init_kernel<<<(M + 255) / 256, 256>>>(deg, M);
    deg_acc_kernel <<<(E + 255) / 256, 256>>>(deg, dst, E);
    dinv_kernel    <<<(M + 255) / 256, 256>>>(dinv, deg, M);

    const int gemm_blocks = (M + 63) / 64;

    // ---- layer 1: 128 -> 128, ReLU ----
    gemm_kernel<128><<<gemm_blocks, 256>>>(x, W1, dinv, hs, agg, M);
    scatter_kernel<128><<<((long long)E * 32 + 255) / 256, 256>>>(src, dst, hs, agg, E);
    finalize_kernel<128, true><<<((long long)M * 32 + 255) / 256, 256>>>(agg, b1, dinv, buf, M);

    // ---- layer 2: 128 -> 128, ReLU ----
    gemm_kernel<128><<<gemm_blocks, 256>>>(buf, W2, dinv, hs, agg, M);
    scatter_kernel<128><<<((long long)E * 32 + 255) / 256, 256>>>(src, dst, hs, agg, E);
    finalize_kernel<128, true><<<((long long)M * 32 + 255) / 256, 256>>>(agg, b2, dinv, buf, M);

    // ---- layer 3: 128 -> 64, no ReLU, write d_out ----
    gemm_kernel<64><<<gemm_blocks, 256>>>(buf, W3, dinv, hs, agg, M);
    scatter_kernel<64><<<((long long)E * 16 + 255) / 256, 256>>>(src, dst, hs, agg, E);
    finalize_kernel<64, false><<<((long long)M * 16 + 255) / 256, 256>>>(agg, b3, dinv, (float*)d_out, M);
}

// round 3
// speedup vs baseline: 1.0043x; 1.0043x over previous
#include <cuda_runtime.h>
#include <cuda_bf16.h>
#include <cstdint>

#define MAX_NODES 100000
#define FEAT 128

// ---------------- scratch (no allocation allowed) ----------------
__device__ float g_hs  [MAX_NODES * FEAT];   // h * dinv[row]  (gather source)
__device__ float g_aggA[MAX_NODES * FEAT];   // accumulator ping
__device__ float g_aggB[MAX_NODES * FEAT];   // accumulator pong
__device__ float g_dinv[MAX_NODES];
__device__ int   g_deg [MAX_NODES];

// ---------------- degree / dinv ----------------
__global__ void deg_init_kernel(int* deg, int M) {
    int i = blockIdx.x * blockDim.x + threadIdx.x;
    if (i < M) deg[i] = 1;                      // self-loop
}
__global__ void deg_acc_kernel(int* deg, const int* __restrict__ dst, int E) {
    int e = blockIdx.x * blockDim.x + threadIdx.x;
    if (e < E) atomicAdd(&deg[dst[e]], 1);
}
__global__ void dinv_kernel(float* dinv, const int* __restrict__ deg, int M) {
    int i = blockIdx.x * blockDim.x + threadIdx.x;
    if (i < M) dinv[i] = rsqrtf((float)deg[i]);
}

// ---------------- tf32 helpers ----------------
__device__ __forceinline__ uint32_t f32_to_tf32(float f) {
    uint32_t r;
    asm("cvt.rna.tf32.f32 %0, %1;" : "=r"(r) : "f"(f));
    return r;
}
__device__ __forceinline__ void split_tf32(float f, uint32_t& hi, uint32_t& lo) {
    hi = f32_to_tf32(f);
    float res = f - __uint_as_float(hi);   // exact in fp32
    lo = f32_to_tf32(res);
}
__device__ __forceinline__ void mma_tf32(float* c, const uint32_t* a, const uint32_t* b) {
    asm volatile(
        "mma.sync.aligned.m16n8k8.row.col.f32.tf32.tf32.f32 "
        "{%0,%1,%2,%3}, {%4,%5,%6,%7}, {%8,%9}, {%0,%1,%2,%3};"
        : "+f"(c[0]), "+f"(c[1]), "+f"(c[2]), "+f"(c[3])
        : "r"(a[0]), "r"(a[1]), "r"(a[2]), "r"(a[3]),
          "r"(b[0]), "r"(b[1]));
}

// ---------------- tensor-core GEMM (tf32x3): hs = agg = f(A) @ W * dinv[row] ----
// A: [M,128] fp32 row-major. W: [128,N] row-major, N in {128,64}.
// If FUSE: A_eff[r][k] = relu(A[r][k]*dinv[r] + bprev[k])  (prev-layer finalize)
// Block: 256 threads (8 warps), tile BM=128 x N. tf32x3 keeps fp32 accuracy.
template <int N, bool FUSE>
__global__ __launch_bounds__(256, 1)
void gemm_mma_kernel(const float* __restrict__ A, const float* __restrict__ W,
                     const float* __restrict__ dinv, const float* __restrict__ bprev,
                     float* __restrict__ hs, float* __restrict__ agg, int M)
{
    constexpr int BM = 128, K = 128, KC = 16;
    constexpr int WARPS_M = (N == 128) ? 4 : 8;
    constexpr int WM = BM / WARPS_M;          // 32 or 16
    constexpr int FM = WM / 16;               // 2 or 1
    constexpr int FN = 8;                     // 64 cols per warp / 8
    constexpr int SA = KC + 4;                // 20 floats: conflict-free A frags
    constexpr int SB = N + 8;                 // 136 / 72: conflict-free B frags

    __shared__ uint32_t As_hi[BM][SA];
    __shared__ uint32_t As_lo[BM][SA];
    __shared__ uint32_t Bs_hi[KC][SB];
    __shared__ uint32_t Bs_lo[KC][SB];

    const int tid   = threadIdx.x;
    const int lane  = tid & 31;
    const int warp  = tid >> 5;
    const int warpM = (N == 128) ? (warp & 3) : warp;
    const int warpN = (N == 128) ? (warp >> 2) : 0;
    const int row0  = blockIdx.x * BM;
    const int g4    = lane >> 2;              // groupID
    const int t4    = lane & 3;               // thread-in-group

    float acc[FM][FN][4];
#pragma unroll
    for (int i = 0; i < FM; i++)
#pragma unroll
        for (int j = 0; j < FN; j++)
#pragma unroll
            for (int q = 0; q < 4; q++) acc[i][j][q] = 0.f;

    // hoist per-row dinv for the fused transform (rows fixed across k-chunks)
    float di_pre[2];
#pragma unroll
    for (int it = 0; it < 2; it++) {
        int grow = row0 + ((it * 256 + tid) >> 2);
        di_pre[it] = (FUSE && grow < M) ? dinv[grow] : 0.f;
    }

    for (int k0 = 0; k0 < K; k0 += KC) {
        // ---- load + transform + split A chunk: 128 x 16 ----
#pragma unroll
        for (int it = 0; it < 2; it++) {
            int lin = it * 256 + tid;          // 0..511 float4 slots
            int r   = lin >> 2;
            int c4  = lin & 3;
            int grow = row0 + r;
            float4 v = make_float4(0.f, 0.f, 0.f, 0.f);
            if (grow < M) {
                v = *(const float4*)(A + (size_t)grow * K + k0 + c4 * 4);
                if (FUSE) {
                    float di = di_pre[it];
                    float4 bb = __ldg((const float4*)(bprev + k0 + c4 * 4));
                    v.x = fmaxf(fmaf(v.x, di, bb.x), 0.f);
                    v.y = fmaxf(fmaf(v.y, di, bb.y), 0.f);
                    v.z = fmaxf(fmaf(v.z, di, bb.z), 0.f);
                    v.w = fmaxf(fmaf(v.w, di, bb.w), 0.f);
                }
            }
            uint4 h, l;
            split_tf32(v.x, h.x, l.x);
            split_tf32(v.y, h.y, l.y);
            split_tf32(v.z, h.z, l.z);
            split_tf32(v.w, h.w, l.w);
            *(uint4*)&As_hi[r][c4 * 4] = h;
            *(uint4*)&As_lo[r][c4 * 4] = l;
        }
        // ---- load + split W chunk: 16 x N ----
        constexpr int BIT = (KC * N / 4) / 256;   // 2 or 1
#pragma unroll
        for (int it = 0; it < BIT; it++) {
            int lin = it * 256 + tid;
            int r   = lin / (N / 4);
            int c4  = lin % (N / 4);
            float4 v = *(const float4*)(W + (size_t)(k0 + r) * N + c4 * 4);
            uint4 h, l;
            split_tf32(v.x, h.x, l.x);
            split_tf32(v.y, h.y, l.y);
            split_tf32(v.z, h.z, l.z);
            split_tf32(v.w, h.w, l.w);
            *(uint4*)&Bs_hi[r][c4 * 4] = h;
            *(uint4*)&Bs_lo[r][c4 * 4] = l;
        }
        __syncthreads();

#pragma unroll
        for (int ks = 0; ks < KC; ks += 8) {
            uint32_t ah[FM][4], al[FM][4];
#pragma unroll
            for (int fm = 0; fm < FM; fm++) {
                int rb = warpM * WM + fm * 16 + g4;
                int cc = ks + t4;
                ah[fm][0] = As_hi[rb    ][cc];
                ah[fm][1] = As_hi[rb + 8][cc];
                ah[fm][2] = As_hi[rb    ][cc + 4];
                ah[fm][3] = As_hi[rb + 8][cc + 4];
                al[fm][0] = As_lo[rb    ][cc];
                al[fm][1] = As_lo[rb + 8][cc];
                al[fm][2] = As_lo[rb    ][cc + 4];
                al[fm][3] = As_lo[rb + 8][cc + 4];
            }
            uint32_t bh[FN][2], bl[FN][2];
#pragma unroll
            for (int fn = 0; fn < FN; fn++) {
                int cn = warpN * 64 + fn * 8 + g4;
                int rk = ks + t4;
                bh[fn][0] = Bs_hi[rk    ][cn];
                bh[fn][1] = Bs_hi[rk + 4][cn];
                bl[fn][0] = Bs_lo[rk    ][cn];
                bl[fn][1] = Bs_lo[rk + 4][cn];
            }
#pragma unroll
            for (int fm = 0; fm < FM; fm++)
#pragma unroll
                for (int fn = 0; fn < FN; fn++) {
                    mma_tf32(acc[fm][fn], ah[fm], bh[fn]);   // hi*hi
                    mma_tf32(acc[fm][fn], ah[fm], bl[fn]);   // hi*lo
                    mma_tf32(acc[fm][fn], al[fm], bh[fn]);   // lo*hi
                }
        }
        __syncthreads();
    }

    // ---- epilogue: scale by dinv[row], write hs and agg (self-loop init) ----
#pragma unroll
    for (int fm = 0; fm < FM; fm++) {
        int r_lo = row0 + warpM * WM + fm * 16 + g4;
        int r_hi = r_lo + 8;
        float d0 = (r_lo < M) ? dinv[r_lo] : 0.f;
        float d1 = (r_hi < M) ? dinv[r_hi] : 0.f;
#pragma unroll
        for (int fn = 0; fn < FN; fn++) {
            int col = warpN * 64 + fn * 8 + t4 * 2;
            if (r_lo < M) {
                float2 v = make_float2(acc[fm][fn][0] * d0, acc[fm][fn][1] * d0);
                *(float2*)(hs  + (size_t)r_lo * N + col) = v;
                *(float2*)(agg + (size_t)r_lo * N + col) = v;
            }
            if (r_hi < M) {
                float2 v = make_float2(acc[fm][fn][2] * d1, acc[fm][fn][3] * d1);
                *(float2*)(hs  + (size_t)r_hi * N + col) = v;
                *(float2*)(agg + (size_t)r_hi * N + col) = v;
            }
        }
    }
}

// ---------------- edge scatter: agg[dst] += hs[src] ----------------
template <int N>
__global__ __launch_bounds__(256)
void scatter_kernel(const int* __restrict__ src, const int* __restrict__ dst,
                    const float* __restrict__ hs, float* __restrict__ agg, int E)
{
    constexpr int CH = N / 4;                   // float4 chunks per row
    int tid = blockIdx.x * blockDim.x + threadIdx.x;
    int eid = tid / CH;
    int j   = tid % CH;
    if (eid >= E) return;
    int s = __ldg(src + eid);
    int d = __ldg(dst + eid);
    float4 v = __ldg((const float4*)(hs + (size_t)s * N) + j);
    float* p = agg + (size_t)d * N + j * 4;
    asm volatile("red.global.add.v4.f32 [%0], {%1,%2,%3,%4};"
                 :: "l"(p), "f"(v.x), "f"(v.y), "f"(v.z), "f"(v.w) : "memory");
}

// ---------------- finalize (layer 3 only): out = agg*dinv + b ----------------
template <int N, bool RELU>
__global__ __launch_bounds__(256)
void finalize_kernel(const float* __restrict__ agg, const float* __restrict__ b,
                     const float* __restrict__ dinv, float* __restrict__ out, int M)
{
    constexpr int CH = N / 4;
    int tid = blockIdx.x * blockDim.x + threadIdx.x;
    if (tid >= M * CH) return;
    int row = tid / CH;
    int j   = tid % CH;
    float di = dinv[row];
    float4 v  = *((const float4*)agg + tid);
    float4 bb = __ldg((const float4*)b + j);
    float4 r;
    r.x = fmaf(v.x, di, bb.x);
    r.y = fmaf(v.y, di, bb.y);
    r.z = fmaf(v.z, di, bb.z);
    r.w = fmaf(v.w, di, bb.w);
    if (RELU) {
        r.x = fmaxf(r.x, 0.f); r.y = fmaxf(r.y, 0.f);
        r.z = fmaxf(r.z, 0.f); r.w = fmaxf(r.w, 0.f);
    }
    ((float4*)out)[tid] = r;
}

// ---------------- launch ----------------
extern "C" void kernel_launch(void* const* d_in, const int* in_sizes, int n_in,
                              void* d_out, int out_size)
{
    const float* x  = (const float*)d_in[0];
    const int*   ei = (const int*)  d_in[1];
    const float* W1 = (const float*)d_in[2];
    const float* b1 = (const float*)d_in[3];
    const float* W2 = (const float*)d_in[4];
    const float* b2 = (const float*)d_in[5];
    const float* W3 = (const float*)d_in[6];
    const float* b3 = (const float*)d_in[7];

    const int M = in_sizes[0] / FEAT;     // 100000
    const int E = in_sizes[1] / 2;        // 800000
    const int* src = ei;
    const int* dst = ei + E;

    float *hs, *aggA, *aggB, *dinv; int* deg;
    cudaGetSymbolAddress((void**)&hs,   g_hs);
    cudaGetSymbolAddress((void**)&aggA, g_aggA);
    cudaGetSymbolAddress((void**)&aggB, g_aggB);
    cudaGetSymbolAddress((void**)&dinv, g_dinv);
    cudaGetSymbolAddress((void**)&deg,  g_deg);

    // degrees + dinv (shared across layers)
    deg_init_kernel<<<(M + 255) / 256, 256>>>(deg, M);
    deg_acc_kernel <<<(E + 255) / 256, 256>>>(deg, dst, E);
    dinv_kernel    <<<(M + 255) / 256, 256>>>(dinv, deg, M);

    const int gemm_blocks = (M + 127) / 128;

    // ---- layer 1: 128 -> 128 ----
    gemm_mma_kernel<128, false><<<gemm_blocks, 256>>>(x, W1, dinv, nullptr, hs, aggA, M);
    scatter_kernel<128><<<((long long)E * 32 + 255) / 256, 256>>>(src, dst, hs, aggA, E);

    // ---- layer 2: 128 -> 128 (finalize of layer 1 fused into A-load) ----
    gemm_mma_kernel<128, true><<<gemm_blocks, 256>>>(aggA, W2, dinv, b1, hs, aggB, M);
    scatter_kernel<128><<<((long long)E * 32 + 255) / 256, 256>>>(src, dst, hs, aggB, E);

    // ---- layer 3: 128 -> 64 (finalize of layer 2 fused), final finalize to d_out ----
    gemm_mma_kernel<64, true><<<gemm_blocks, 256>>>(aggB, W3, dinv, b2, hs, aggA, M);
    scatter_kernel<64><<<((long long)E * 16 + 255) / 256, 256>>>(src, dst, hs, aggA, E);
    finalize_kernel<64, false><<<((long long)M * 16 + 255) / 256, 256>>>(aggA, b3, dinv, (float*)d_out, M);
}

// round 4
// speedup vs baseline: 1.0234x; 1.0190x over previous
#include <cuda_runtime.h>
#include <cuda_bf16.h>
#include <cstdint>

#define MAX_NODES 100000
#define FEAT 128

// ---------------- scratch (no allocation allowed) ----------------
__device__ float g_hs  [MAX_NODES * FEAT];   // h * dinv[row]  (gather source)
__device__ float g_aggA[MAX_NODES * FEAT];   // accumulator ping
__device__ float g_aggB[MAX_NODES * FEAT];   // accumulator pong
__device__ float g_dinv[MAX_NODES];
__device__ int   g_deg [MAX_NODES];

// ---------------- degree / dinv ----------------
__global__ void deg_init_kernel(int* deg, int M) {
    int i = blockIdx.x * blockDim.x + threadIdx.x;
    if (i < M) deg[i] = 1;                      // self-loop
}
__global__ void deg_acc_kernel(int* deg, const int* __restrict__ dst, int E) {
    int e = blockIdx.x * blockDim.x + threadIdx.x;
    if (e < E) atomicAdd(&deg[dst[e]], 1);
}
__global__ void dinv_kernel(float* dinv, const int* __restrict__ deg, int M) {
    int i = blockIdx.x * blockDim.x + threadIdx.x;
    if (i < M) dinv[i] = rsqrtf((float)deg[i]);
}

// ---------------- tf32 / mma / cp.async helpers ----------------
__device__ __forceinline__ uint32_t f32_to_tf32(float f) {
    uint32_t r;
    asm("cvt.rna.tf32.f32 %0, %1;" : "=r"(r) : "f"(f));
    return r;
}
__device__ __forceinline__ void split_tf32(float f, uint32_t& hi, uint32_t& lo) {
    hi = f32_to_tf32(f);
    float res = f - __uint_as_float(hi);   // exact in fp32
    lo = f32_to_tf32(res);
}
__device__ __forceinline__ void mma_tf32(float* c, const uint32_t* a, const uint32_t* b) {
    asm volatile(
        "mma.sync.aligned.m16n8k8.row.col.f32.tf32.tf32.f32 "
        "{%0,%1,%2,%3}, {%4,%5,%6,%7}, {%8,%9}, {%0,%1,%2,%3};"
        : "+f"(c[0]), "+f"(c[1]), "+f"(c[2]), "+f"(c[3])
        : "r"(a[0]), "r"(a[1]), "r"(a[2]), "r"(a[3]),
          "r"(b[0]), "r"(b[1]));
}
__device__ __forceinline__ void cp_async16(uint32_t saddr, const void* gaddr, bool pred) {
    int sz = pred ? 16 : 0;
    asm volatile("cp.async.cg.shared.global [%0], [%1], 16, %2;"
                 :: "r"(saddr), "l"(gaddr), "r"(sz));
}
__device__ __forceinline__ void cp_commit() {
    asm volatile("cp.async.commit_group;" ::: "memory");
}
template <int NN>
__device__ __forceinline__ void cp_wait() {
    asm volatile("cp.async.wait_group %0;" :: "n"(NN) : "memory");
}

// ---------------- tensor-core GEMM (tf32x3, cp.async pipelined) --------------
// hs = agg = f(A) @ W * dinv[row]; if FUSE: f(a) = relu(a*dinv[row] + bprev[k])
// A: [M,128] fp32 row-major. W: [128,N] row-major, N in {128,64}.
// 512 threads (16 warps), tile BM=128 x N, warp tile 32x32 (N=128) / 16x32.
template <int N, bool FUSE>
__global__ __launch_bounds__(512, 1)
void gemm_mma_kernel(const float* __restrict__ A, const float* __restrict__ W,
                     const float* __restrict__ dinv, const float* __restrict__ bprev,
                     float* __restrict__ hs, float* __restrict__ agg, int M)
{
    constexpr int BM = 128, K = 128, KC = 16, CHUNKS = K / KC;
    constexpr int SA = KC + 4;                 // 20: conflict-free A frag LDS
    constexpr int SB = N + 8;                  // 136 / 72: conflict-free B frag LDS
    constexpr int WN = 32;
    constexpr int WARPSN = N / WN;             // 4 (N=128) or 2 (N=64)
    constexpr int WM = (N == 128) ? 32 : 16;
    constexpr int FM = WM / 16;                // 2 or 1
    constexpr int FN = 4;

    __shared__ float As[2][BM][SA];            // 2 x 10 KB
    __shared__ float Ws[2][KC][SB];            // 2 x 8.7 / 4.6 KB
    __shared__ float bs[K];

    const int tid   = threadIdx.x;
    const int lane  = tid & 31;
    const int warp  = tid >> 5;
    const int warpN = warp % WARPSN;
    const int warpM = warp / WARPSN;
    const int row0  = blockIdx.x * BM;
    const int g4    = lane >> 2;
    const int t4    = lane & 3;

    if (FUSE && tid < K) bs[tid] = bprev[tid];

    float acc[FM][FN][4];
#pragma unroll
    for (int i = 0; i < FM; i++)
#pragma unroll
        for (int j = 0; j < FN; j++)
#pragma unroll
            for (int q = 0; q < 4; q++) acc[i][j][q] = 0.f;

    // per-warp-row dinv (used for FUSE input transform AND epilogue scale)
    float dv[FM][2];
#pragma unroll
    for (int fm = 0; fm < FM; fm++) {
        int r = row0 + warpM * WM + fm * 16 + g4;
        dv[fm][0] = (r     < M) ? dinv[r]     : 0.f;
        dv[fm][1] = (r + 8 < M) ? dinv[r + 8] : 0.f;
    }

    // ---- async chunk issue: A 128x16 (1 float4/thread), W 16xN ----
    auto issue = [&](int cc) {
        int k0 = cc * KC;
        int buf = cc & 1;
        {
            int r  = tid >> 2;
            int c4 = (tid & 3) * 4;
            bool p = (row0 + r) < M;
            cp_async16((uint32_t)__cvta_generic_to_shared(&As[buf][r][c4]),
                       A + (size_t)(row0 + r) * K + k0 + c4, p);
        }
        if (N == 128 || tid < 256) {
            int r  = tid / (N / 4);
            int c4 = (tid % (N / 4)) * 4;
            cp_async16((uint32_t)__cvta_generic_to_shared(&Ws[buf][r][c4]),
                       W + (size_t)(k0 + r) * N + c4, true);
        }
        cp_commit();
    };

    issue(0);

    for (int c = 0; c < CHUNKS; c++) {
        if (c + 1 < CHUNKS) { issue(c + 1); cp_wait<1>(); }
        else                { cp_wait<0>(); }
        __syncthreads();

        const int buf = c & 1;
        const int k0  = c * KC;

#pragma unroll
        for (int ks = 0; ks < KC; ks += 8) {
            // ---- A fragments: load fp32, (FUSE-transform), split ----
            uint32_t ah[FM][4], al[FM][4];
#pragma unroll
            for (int fm = 0; fm < FM; fm++) {
                int rb = warpM * WM + fm * 16 + g4;
                float v0 = As[buf][rb    ][ks + t4];
                float v1 = As[buf][rb + 8][ks + t4];
                float v2 = As[buf][rb    ][ks + t4 + 4];
                float v3 = As[buf][rb + 8][ks + t4 + 4];
                if (FUSE) {
                    float b0 = bs[k0 + ks + t4];
                    float b4 = bs[k0 + ks + t4 + 4];
                    v0 = fmaxf(fmaf(v0, dv[fm][0], b0), 0.f);
                    v1 = fmaxf(fmaf(v1, dv[fm][1], b0), 0.f);
                    v2 = fmaxf(fmaf(v2, dv[fm][0], b4), 0.f);
                    v3 = fmaxf(fmaf(v3, dv[fm][1], b4), 0.f);
                }
                split_tf32(v0, ah[fm][0], al[fm][0]);
                split_tf32(v1, ah[fm][1], al[fm][1]);
                split_tf32(v2, ah[fm][2], al[fm][2]);
                split_tf32(v3, ah[fm][3], al[fm][3]);
            }
            // ---- B fragments ----
            uint32_t bh[FN][2], bl[FN][2];
#pragma unroll
            for (int fn = 0; fn < FN; fn++) {
                int cn = warpN * WN + fn * 8 + g4;
                split_tf32(Ws[buf][ks + t4    ][cn], bh[fn][0], bl[fn][0]);
                split_tf32(Ws[buf][ks + t4 + 4][cn], bh[fn][1], bl[fn][1]);
            }
#pragma unroll
            for (int fm = 0; fm < FM; fm++)
#pragma unroll
                for (int fn = 0; fn < FN; fn++) {
                    mma_tf32(acc[fm][fn], ah[fm], bh[fn]);   // hi*hi
                    mma_tf32(acc[fm][fn], ah[fm], bl[fn]);   // hi*lo
                    mma_tf32(acc[fm][fn], al[fm], bh[fn]);   // lo*hi
                }
        }
        __syncthreads();
    }

    // ---- epilogue: scale by dinv[row], write hs and agg (self-loop init) ----
#pragma unroll
    for (int fm = 0; fm < FM; fm++) {
        int r_lo = row0 + warpM * WM + fm * 16 + g4;
        int r_hi = r_lo + 8;
        float d0 = dv[fm][0];
        float d1 = dv[fm][1];
#pragma unroll
        for (int fn = 0; fn < FN; fn++) {
            int col = warpN * WN + fn * 8 + t4 * 2;
            if (r_lo < M) {
                float2 v = make_float2(acc[fm][fn][0] * d0, acc[fm][fn][1] * d0);
                *(float2*)(hs  + (size_t)r_lo * N + col) = v;
                *(float2*)(agg + (size_t)r_lo * N + col) = v;
            }
            if (r_hi < M) {
                float2 v = make_float2(acc[fm][fn][2] * d1, acc[fm][fn][3] * d1);
                *(float2*)(hs  + (size_t)r_hi * N + col) = v;
                *(float2*)(agg + (size_t)r_hi * N + col) = v;
            }
        }
    }
}

// ---------------- edge scatter: agg[dst] += hs[src] ----------------
template <int N>
__global__ __launch_bounds__(256)
void scatter_kernel(const int* __restrict__ src, const int* __restrict__ dst,
                    const float* __restrict__ hs, float* __restrict__ agg, int E)
{
    constexpr int CH = N / 4;                   // float4 chunks per row
    int tid = blockIdx.x * blockDim.x + threadIdx.x;
    int eid = tid / CH;
    int j   = tid % CH;
    if (eid >= E) return;
    int s = __ldg(src + eid);
    int d = __ldg(dst + eid);
    float4 v = __ldg((const float4*)(hs + (size_t)s * N) + j);
    float* p = agg + (size_t)d * N + j * 4;
    asm volatile("red.global.add.v4.f32 [%0], {%1,%2,%3,%4};"
                 :: "l"(p), "f"(v.x), "f"(v.y), "f"(v.z), "f"(v.w) : "memory");
}

// ---------------- finalize (layer 3 only): out = agg*dinv + b ----------------
template <int N, bool RELU>
__global__ __launch_bounds__(256)
void finalize_kernel(const float* __restrict__ agg, const float* __restrict__ b,
                     const float* __restrict__ dinv, float* __restrict__ out, int M)
{
    constexpr int CH = N / 4;
    int tid = blockIdx.x * blockDim.x + threadIdx.x;
    if (tid >= M * CH) return;
    int row = tid / CH;
    int j   = tid % CH;
    float di = dinv[row];
    float4 v  = *((const float4*)agg + tid);
    float4 bb = __ldg((const float4*)b + j);
    float4 r;
    r.x = fmaf(v.x, di, bb.x);
    r.y = fmaf(v.y, di, bb.y);
    r.z = fmaf(v.z, di, bb.z);
    r.w = fmaf(v.w, di, bb.w);
    if (RELU) {
        r.x = fmaxf(r.x, 0.f); r.y = fmaxf(r.y, 0.f);
        r.z = fmaxf(r.z, 0.f); r.w = fmaxf(r.w, 0.f);
    }
    ((float4*)out)[tid] = r;
}

// ---------------- launch ----------------
extern "C" void kernel_launch(void* const* d_in, const int* in_sizes, int n_in,
                              void* d_out, int out_size)
{
    const float* x  = (const float*)d_in[0];
    const int*   ei = (const int*)  d_in[1];
    const float* W1 = (const float*)d_in[2];
    const float* b1 = (const float*)d_in[3];
    const float* W2 = (const float*)d_in[4];
    const float* b2 = (const float*)d_in[5];
    const float* W3 = (const float*)d_in[6];
    const float* b3 = (const float*)d_in[7];

    const int M = in_sizes[0] / FEAT;     // 100000
    const int E = in_sizes[1] / 2;        // 800000
    const int* src = ei;
    const int* dst = ei + E;

    float *hs, *aggA, *aggB, *dinv; int* deg;
    cudaGetSymbolAddress((void**)&hs,   g_hs);
    cudaGetSymbolAddress((void**)&aggA, g_aggA);
    cudaGetSymbolAddress((void**)&aggB, g_aggB);
    cudaGetSymbolAddress((void**)&dinv, g_dinv);
    cudaGetSymbolAddress((void**)&deg,  g_deg);

    // degrees + dinv (shared across layers)
    deg_init_kernel<<<(M + 255) / 256, 256>>>(deg, M);
    deg_acc_kernel <<<(E + 255) / 256, 256>>>(deg, dst, E);
    dinv_kernel    <<<(M + 255) / 256, 256>>>(dinv, deg, M);

    const int gemm_blocks = (M + 127) / 128;

    // ---- layer 1: 128 -> 128 ----
    gemm_mma_kernel<128, false><<<gemm_blocks, 512>>>(x, W1, dinv, nullptr, hs, aggA, M);
    scatter_kernel<128><<<((long long)E * 32 + 255) / 256, 256>>>(src, dst, hs, aggA, E);

    // ---- layer 2: 128 -> 128 (finalize of layer 1 fused into A path) ----
    gemm_mma_kernel<128, true><<<gemm_blocks, 512>>>(aggA, W2, dinv, b1, hs, aggB, M);
    scatter_kernel<128><<<((long long)E * 32 + 255) / 256, 256>>>(src, dst, hs, aggB, E);

    // ---- layer 3: 128 -> 64 (finalize of layer 2 fused), final finalize to d_out ----
    gemm_mma_kernel<64, true><<<gemm_blocks, 512>>>(aggB, W3, dinv, b2, hs, aggA, M);
    scatter_kernel<64><<<((long long)E * 16 + 255) / 256, 256>>>(src, dst, hs, aggA, E);
    finalize_kernel<64, false><<<((long long)M * 16 + 255) / 256, 256>>>(aggA, b3, dinv, (float*)d_out, M);
}

// round 6
// speedup vs baseline: 1.3717x; 1.3403x over previous
#include <cuda_runtime.h>
#include <cuda_bf16.h>
#include <cstdint>

#define MAX_NODES 100000
#define MAX_EDGES 800000
#define FEAT 128

// ---------------- scratch (no allocation allowed) ----------------
__device__ float g_hs  [MAX_NODES * FEAT];   // h * dinv[row]  (gather source)
__device__ float g_agg [MAX_NODES * FEAT];   // aggregated output per layer
__device__ float g_dinv[MAX_NODES];
__device__ int   g_deg [MAX_NODES];          // degree incl self-loop
__device__ int   g_rowstart[MAX_NODES];      // CSR row start (edges only)
__device__ int   g_cursor  [MAX_NODES];
__device__ int   g_csr_src [MAX_EDGES];
__device__ int   g_bsum [128];
__device__ int   g_bscan[128];
// pre-split weights (tf32 hi/lo): W1 @0 (16384), W2 @16384, W3 @32768 (8192)
__device__ uint32_t g_whi[40960];
__device__ uint32_t g_wlo[40960];

// ---------------- degree / dinv ----------------
__global__ void deg_init_kernel(int* deg, int M) {
    int i = blockIdx.x * blockDim.x + threadIdx.x;
    if (i < M) deg[i] = 1;                      // self-loop
}
__global__ void deg_acc_kernel(int* deg, const int* __restrict__ dst, int E) {
    int e = blockIdx.x * blockDim.x + threadIdx.x;
    if (e < E) atomicAdd(&deg[dst[e]], 1);
}
__global__ void dinv_kernel(float* dinv, const int* __restrict__ deg, int M) {
    int i = blockIdx.x * blockDim.x + threadIdx.x;
    if (i < M) dinv[i] = rsqrtf((float)deg[i]);
}

// ---------------- CSR build (counting placement by dst) ----------------
__global__ __launch_bounds__(1024)
void scan_block_kernel(const int* __restrict__ deg, int* rowstart, int* bsum, int M) {
    __shared__ int sh[1024];
    int tid = threadIdx.x;
    int i   = blockIdx.x * 1024 + tid;
    int v   = (i < M) ? (deg[i] - 1) : 0;
    sh[tid] = v;
    __syncthreads();
#pragma unroll
    for (int off = 1; off < 1024; off <<= 1) {
        int t = (tid >= off) ? sh[tid - off] : 0;
        __syncthreads();
        sh[tid] += t;
        __syncthreads();
    }
    if (i < M) rowstart[i] = sh[tid] - v;       // exclusive within block
    if (tid == 1023) bsum[blockIdx.x] = sh[1023];
}
__global__ __launch_bounds__(128)
void scan_tops_kernel(const int* __restrict__ bsum, int* bscan, int nb) {
    __shared__ int sh[128];
    int tid = threadIdx.x;
    int v = (tid < nb) ? bsum[tid] : 0;
    sh[tid] = v;
    __syncthreads();
#pragma unroll
    for (int off = 1; off < 128; off <<= 1) {
        int t = (tid >= off) ? sh[tid - off] : 0;
        __syncthreads();
        sh[tid] += t;
        __syncthreads();
    }
    bscan[tid] = sh[tid] - v;
}
__global__ void scan_fix_kernel(int* rowstart, int* cursor, const int* __restrict__ bscan, int M) {
    int i = blockIdx.x * blockDim.x + threadIdx.x;
    if (i < M) {
        int r = rowstart[i] + bscan[i >> 10];
        rowstart[i] = r;
        cursor[i]   = r;
    }
}
__global__ void csr_fill_kernel(const int* __restrict__ src, const int* __restrict__ dst,
                                int* cursor, int* csr_src, int E) {
    int e = blockIdx.x * blockDim.x + threadIdx.x;
    if (e < E) {
        int d = dst[e];
        int pos = atomicAdd(&cursor[d], 1);
        csr_src[pos] = src[e];
    }
}

// ---------------- tf32 / mma / cp.async helpers ----------------
__device__ __forceinline__ uint32_t f32_to_tf32(float f) {
    uint32_t r;
    asm("cvt.rna.tf32.f32 %0, %1;" : "=r"(r) : "f"(f));
    return r;
}
__device__ __forceinline__ void split_tf32(float f, uint32_t& hi, uint32_t& lo) {
    hi = f32_to_tf32(f);
    float res = f - __uint_as_float(hi);   // exact in fp32
    lo = f32_to_tf32(res);
}
__device__ __forceinline__ void mma_tf32(float* c, const uint32_t* a, const uint32_t* b) {
    asm volatile(
        "mma.sync.aligned.m16n8k8.row.col.f32.tf32.tf32.f32 "
        "{%0,%1,%2,%3}, {%4,%5,%6,%7}, {%8,%9}, {%0,%1,%2,%3};"
        : "+f"(c[0]), "+f"(c[1]), "+f"(c[2]), "+f"(c[3])
        : "r"(a[0]), "r"(a[1]), "r"(a[2]), "r"(a[3]),
          "r"(b[0]), "r"(b[1]));
}
__device__ __forceinline__ void cp_async16(uint32_t saddr, const void* gaddr, bool pred) {
    int sz = pred ? 16 : 0;
    asm volatile("cp.async.cg.shared.global [%0], [%1], 16, %2;"
                 :: "r"(saddr), "l"(gaddr), "r"(sz));
}
__device__ __forceinline__ void cp_commit() {
    asm volatile("cp.async.commit_group;" ::: "memory");
}
template <int NN>
__device__ __forceinline__ void cp_wait() {
    asm volatile("cp.async.wait_group %0;" :: "n"(NN) : "memory");
}

// ---------------- split W into tf32 hi/lo ----------------
__global__ void split_w_kernel(const float* __restrict__ W, uint32_t* whi, uint32_t* wlo, int L) {
    int i = blockIdx.x * blockDim.x + threadIdx.x;
    if (i < L) {
        uint32_t h, l;
        split_tf32(W[i], h, l);
        whi[i] = h;
        wlo[i] = l;
    }
}

// ---------------- tensor-core GEMM (tf32x3, cp.async pipelined, KC=8) --------
// hs = f(A) @ W * dinv[row]; if FUSE: f(a) = relu(a*dinv[row] + bprev[k])
// A: [M,128] fp32 row-major. W pre-split tf32 hi/lo: [128,N], N in {128,64}.
template <int N, bool FUSE>
__global__ __launch_bounds__(512, 1)
void gemm_mma_kernel(const float* __restrict__ A,
                     const uint32_t* __restrict__ Whi, const uint32_t* __restrict__ Wlo,
                     const float* __restrict__ dinv, const float* __restrict__ bprev,
                     float* __restrict__ hs, int M)
{
    constexpr int BM = 128, K = 128, KC = 8, CHUNKS = K / KC;
    constexpr int SA = KC + 4;                 // 12: conflict-free A frag LDS
    constexpr int SB = N + 8;                  // 136 / 72
    constexpr int WN = 32;
    constexpr int WARPSN = N / WN;             // 4 or 2
    constexpr int WM = (N == 128) ? 32 : 16;
    constexpr int FM = WM / 16;                // 2 or 1
    constexpr int FN = 4;

    __shared__ float    As   [2][BM][SA];      // 12.3 KB
    __shared__ uint32_t Bs_hi[2][KC][SB];      // 8.7 / 4.6 KB
    __shared__ uint32_t Bs_lo[2][KC][SB];
    __shared__ float    bs[K];

    const int tid   = threadIdx.x;
    const int lane  = tid & 31;
    const int warp  = tid >> 5;
    const int warpN = warp % WARPSN;
    const int warpM = warp / WARPSN;
    const int row0  = blockIdx.x * BM;
    const int g4    = lane >> 2;
    const int t4    = lane & 3;

    if (FUSE && tid < K) bs[tid] = bprev[tid];

    float acc[FM][FN][4];
#pragma unroll
    for (int i = 0; i < FM; i++)
#pragma unroll
        for (int j = 0; j < FN; j++)
#pragma unroll
            for (int q = 0; q < 4; q++) acc[i][j][q] = 0.f;

    float dv[FM][2];
#pragma unroll
    for (int fm = 0; fm < FM; fm++) {
        int r = row0 + warpM * WM + fm * 16 + g4;
        dv[fm][0] = (r     < M) ? dinv[r]     : 0.f;
        dv[fm][1] = (r + 8 < M) ? dinv[r + 8] : 0.f;
    }

    auto issue = [&](int cc) {
        int k0  = cc * KC;
        int buf = cc & 1;
        if (tid < 256) {   // A: 128x8 fp32 = 256 float4
            int r  = tid >> 1;
            int c4 = (tid & 1) * 4;
            bool p = (row0 + r) < M;
            cp_async16((uint32_t)__cvta_generic_to_shared(&As[buf][r][c4]),
                       A + (size_t)(row0 + r) * K + k0 + c4, p);
        }
        if (N == 128) {    // Whi/Wlo: 8x128 = 256 uint4 each
            if (tid >= 256) {
                int t = tid - 256;
                int r = t >> 5, c = (t & 31) * 4;
                cp_async16((uint32_t)__cvta_generic_to_shared(&Bs_hi[buf][r][c]),
                           Whi + (size_t)(k0 + r) * N + c, true);
            } else {
                int r = tid >> 5, c = (tid & 31) * 4;
                cp_async16((uint32_t)__cvta_generic_to_shared(&Bs_lo[buf][r][c]),
                           Wlo + (size_t)(k0 + r) * N + c, true);
            }
        } else {           // 8x64 = 128 uint4 each
            if (tid >= 256 && tid < 384) {
                int t = tid - 256;
                int r = t >> 4, c = (t & 15) * 4;
                cp_async16((uint32_t)__cvta_generic_to_shared(&Bs_hi[buf][r][c]),
                           Whi + (size_t)(k0 + r) * N + c, true);
            } else if (tid >= 384) {
                int t = tid - 384;
                int r = t >> 4, c = (t & 15) * 4;
                cp_async16((uint32_t)__cvta_generic_to_shared(&Bs_lo[buf][r][c]),
                           Wlo + (size_t)(k0 + r) * N + c, true);
            }
        }
        cp_commit();
    };

    issue(0);

    for (int c = 0; c < CHUNKS; c++) {
        if (c + 1 < CHUNKS) { issue(c + 1); cp_wait<1>(); }
        else                { cp_wait<0>(); }
        __syncthreads();

        const int buf = c & 1;
        const int k0  = c * KC;

        // one m16n8k8 K-step per chunk (KC=8)
        uint32_t ah[FM][4], al[FM][4];
#pragma unroll
        for (int fm = 0; fm < FM; fm++) {
            int rb = warpM * WM + fm * 16 + g4;
            float v0 = As[buf][rb    ][t4];
            float v1 = As[buf][rb + 8][t4];
            float v2 = As[buf][rb    ][t4 + 4];
            float v3 = As[buf][rb + 8][t4 + 4];
            if (FUSE) {
                float b0 = bs[k0 + t4];
                float b4 = bs[k0 + t4 + 4];
                v0 = fmaxf(fmaf(v0, dv[fm][0], b0), 0.f);
                v1 = fmaxf(fmaf(v1, dv[fm][1], b0), 0.f);
                v2 = fmaxf(fmaf(v2, dv[fm][0], b4), 0.f);
                v3 = fmaxf(fmaf(v3, dv[fm][1], b4), 0.f);
            }
            split_tf32(v0, ah[fm][0], al[fm][0]);
            split_tf32(v1, ah[fm][1], al[fm][1]);
            split_tf32(v2, ah[fm][2], al[fm][2]);
            split_tf32(v3, ah[fm][3], al[fm][3]);
        }
        uint32_t bh[FN][2], bl[FN][2];
#pragma unroll
        for (int fn = 0; fn < FN; fn++) {
            int cn = warpN * WN + fn * 8 + g4;
            bh[fn][0] = Bs_hi[buf][t4    ][cn];
            bh[fn][1] = Bs_hi[buf][t4 + 4][cn];
            bl[fn][0] = Bs_lo[buf][t4    ][cn];
            bl[fn][1] = Bs_lo[buf][t4 + 4][cn];
        }
#pragma unroll
        for (int fm = 0; fm < FM; fm++)
#pragma unroll
            for (int fn = 0; fn < FN; fn++) {
                mma_tf32(acc[fm][fn], ah[fm], bh[fn]);   // hi*hi
                mma_tf32(acc[fm][fn], ah[fm], bl[fn]);   // hi*lo
                mma_tf32(acc[fm][fn], al[fm], bh[fn]);   // lo*hi
            }
        __syncthreads();
    }

    // epilogue: scale by dinv[row], write hs only
#pragma unroll
    for (int fm = 0; fm < FM; fm++) {
        int r_lo = row0 + warpM * WM + fm * 16 + g4;
        int r_hi = r_lo + 8;
        float d0 = dv[fm][0];
        float d1 = dv[fm][1];
#pragma unroll
        for (int fn = 0; fn < FN; fn++) {
            int col = warpN * WN + fn * 8 + t4 * 2;
            if (r_lo < M)
                *(float2*)(hs + (size_t)r_lo * N + col) =
                    make_float2(acc[fm][fn][0] * d0, acc[fm][fn][1] * d0);
            if (r_hi < M)
                *(float2*)(hs + (size_t)r_hi * N + col) =
                    make_float2(acc[fm][fn][2] * d1, acc[fm][fn][3] * d1);
        }
    }
}

// ---------------- CSR aggregate: out[d] = hs[d] + sum_{s in N(d)} hs[s] -------
// FINAL: out[d] = (...)*dinv[d] + bias  (layer 3 writes d_out directly)
template <int N, bool FINAL>
__global__ __launch_bounds__(256)
void aggregate_kernel(const int* __restrict__ csr_src, const int* __restrict__ rowstart,
                      const int* __restrict__ deg, const float* __restrict__ hs,
                      const float* __restrict__ dinv, const float* __restrict__ bias,
                      float* __restrict__ out, int M)
{
    constexpr int CH  = N / 4;               // float4 chunks per row
    constexpr int NPW = 32 / CH;             // nodes per warp: 1 (N=128) / 2 (N=64)
    int warpId = (blockIdx.x * blockDim.x + threadIdx.x) >> 5;
    int lane   = threadIdx.x & 31;
    int g      = lane / CH;
    int j      = lane % CH;
    int node   = warpId * NPW + g;
    if (node >= M) return;

    const float4* hsv = (const float4*)hs;
    float4 acc = __ldg(hsv + (size_t)node * CH + j);     // self-loop term
    int beg = rowstart[node];
    int cnt = deg[node] - 1;
    for (int e = 0; e < cnt; e++) {
        int s = __ldg(csr_src + beg + e);
        float4 v = __ldg(hsv + (size_t)s * CH + j);
        acc.x += v.x; acc.y += v.y; acc.z += v.z; acc.w += v.w;
    }
    if (FINAL) {
        float di = dinv[node];
        float4 bb = __ldg((const float4*)bias + j);
        acc.x = fmaf(acc.x, di, bb.x);
        acc.y = fmaf(acc.y, di, bb.y);
        acc.z = fmaf(acc.z, di, bb.z);
        acc.w = fmaf(acc.w, di, bb.w);
    }
    ((float4*)out)[(size_t)node * CH + j] = acc;
}

// ---------------- launch ----------------
extern "C" void kernel_launch(void* const* d_in, const int* in_sizes, int n_in,
                              void* d_out, int out_size)
{
    const float* x  = (const float*)d_in[0];
    const int*   ei = (const int*)  d_in[1];
    const float* W1 = (const float*)d_in[2];
    const float* b1 = (const float*)d_in[3];
    const float* W2 = (const float*)d_in[4];
    const float* b2 = (const float*)d_in[5];
    const float* W3 = (const float*)d_in[6];
    const float* b3 = (const float*)d_in[7];

    const int M = in_sizes[0] / FEAT;     // 100000
    const int E = in_sizes[1] / 2;        // 800000
    const int* src = ei;
    const int* dst = ei + E;

    float *hs, *agg, *dinv; int *deg, *rowstart, *cursor, *csr_src, *bsum, *bscan;
    uint32_t *whi, *wlo;
    cudaGetSymbolAddress((void**)&hs,       g_hs);
    cudaGetSymbolAddress((void**)&agg,      g_agg);
    cudaGetSymbolAddress((void**)&dinv,     g_dinv);
    cudaGetSymbolAddress((void**)&deg,      g_deg);
    cudaGetSymbolAddress((void**)&rowstart, g_rowstart);
    cudaGetSymbolAddress((void**)&cursor,   g_cursor);
    cudaGetSymbolAddress((void**)&csr_src,  g_csr_src);
    cudaGetSymbolAddress((void**)&bsum,     g_bsum);
    cudaGetSymbolAddress((void**)&bscan,    g_bscan);
    cudaGetSymbolAddress((void**)&whi,      g_whi);
    cudaGetSymbolAddress((void**)&wlo,      g_wlo);

    // degrees + dinv
    deg_init_kernel<<<(M + 255) / 256, 256>>>(deg, M);
    deg_acc_kernel <<<(E + 255) / 256, 256>>>(deg, dst, E);
    dinv_kernel    <<<(M + 255) / 256, 256>>>(dinv, deg, M);

    // CSR build (by dst)
    int nb = (M + 1023) / 1024;
    scan_block_kernel<<<nb, 1024>>>(deg, rowstart, bsum, M);
    scan_tops_kernel <<<1, 128>>>(bsum, bscan, nb);
    scan_fix_kernel  <<<(M + 255) / 256, 256>>>(rowstart, cursor, bscan, M);
    csr_fill_kernel  <<<(E + 255) / 256, 256>>>(src, dst, cursor, csr_src, E);

    // pre-split weights
    split_w_kernel<<<(16384 + 255) / 256, 256>>>(W1, whi,         wlo,         16384);
    split_w_kernel<<<(16384 + 255) / 256, 256>>>(W2, whi + 16384, wlo + 16384, 16384);
    split_w_kernel<<<( 8192 + 255) / 256, 256>>>(W3, whi + 32768, wlo + 32768,  8192);

    const int gemm_blocks = (M + 127) / 128;
    const int agg_blocks_128 = (M * 32 + 255) / 256;         // 1 node / warp
    const int agg_blocks_64  = (M * 16 + 255) / 256;         // 2 nodes / warp

    // ---- layer 1: 128 -> 128 ----
    gemm_mma_kernel<128, false><<<gemm_blocks, 512>>>(x, whi, wlo, dinv, nullptr, hs, M);
    aggregate_kernel<128, false><<<agg_blocks_128, 256>>>(csr_src, rowstart, deg, hs, dinv, nullptr, agg, M);

    // ---- layer 2: 128 -> 128 (layer-1 finalize fused into A path) ----
    gemm_mma_kernel<128, true><<<gemm_blocks, 512>>>(agg, whi + 16384, wlo + 16384, dinv, b1, hs, M);
    aggregate_kernel<128, false><<<agg_blocks_128, 256>>>(csr_src, rowstart, deg, hs, dinv, nullptr, agg, M);

    // ---- layer 3: 128 -> 64 (layer-2 finalize fused); final aggregate writes d_out ----
    gemm_mma_kernel<64, true><<<gemm_blocks, 512>>>(agg, whi + 32768, wlo + 32768, dinv, b2, hs, M);
    aggregate_kernel<64, true><<<agg_blocks_64, 256>>>(csr_src, rowstart, deg, hs, dinv, b3, (float*)d_out, M);
}

// round 7
// speedup vs baseline: 1.7283x; 1.2600x over previous
#include <cuda_runtime.h>
#include <cuda_bf16.h>
#include <cstdint>

#define MAX_NODES 100000
#define MAX_EDGES 800000
#define FEAT 128

// ---------------- scratch (no allocation allowed) ----------------
__device__ float g_hs  [MAX_NODES * FEAT];   // h * dinv[row]  (gather source)
__device__ float g_agg [MAX_NODES * FEAT];   // aggregated output per layer
__device__ float g_dinv[MAX_NODES];
__device__ int   g_deg [MAX_NODES];          // degree incl self-loop
__device__ int   g_rowstart[MAX_NODES];      // CSR row start (edges only)
__device__ int   g_cursor  [MAX_NODES];
__device__ int   g_csr_src [MAX_EDGES];
__device__ int   g_bsum [128];
__device__ int   g_bscan[128];
// pre-split packed bf16 weights (hi/lo), [K/2 x N] u32 each:
// W1 @0 (8192), W2 @8192 (8192), W3 @16384 (4096)
__device__ uint32_t g_whi[20480];
__device__ uint32_t g_wlo[20480];

// ---------------- degree / dinv ----------------
__global__ void deg_init_kernel(int* deg, int M) {
    int i = blockIdx.x * blockDim.x + threadIdx.x;
    if (i < M) deg[i] = 1;                      // self-loop
}
__global__ void deg_acc_kernel(int* deg, const int* __restrict__ dst, int E) {
    int e = blockIdx.x * blockDim.x + threadIdx.x;
    if (e < E) atomicAdd(&deg[dst[e]], 1);
}
__global__ void dinv_kernel(float* dinv, const int* __restrict__ deg, int M) {
    int i = blockIdx.x * blockDim.x + threadIdx.x;
    if (i < M) dinv[i] = rsqrtf((float)deg[i]);
}

// ---------------- CSR build (counting placement by dst) ----------------
__global__ __launch_bounds__(1024)
void scan_block_kernel(const int* __restrict__ deg, int* rowstart, int* bsum, int M) {
    __shared__ int sh[1024];
    int tid = threadIdx.x;
    int i   = blockIdx.x * 1024 + tid;
    int v   = (i < M) ? (deg[i] - 1) : 0;
    sh[tid] = v;
    __syncthreads();
#pragma unroll
    for (int off = 1; off < 1024; off <<= 1) {
        int t = (tid >= off) ? sh[tid - off] : 0;
        __syncthreads();
        sh[tid] += t;
        __syncthreads();
    }
    if (i < M) rowstart[i] = sh[tid] - v;       // exclusive within block
    if (tid == 1023) bsum[blockIdx.x] = sh[1023];
}
__global__ __launch_bounds__(128)
void scan_tops_kernel(const int* __restrict__ bsum, int* bscan, int nb) {
    __shared__ int sh[128];
    int tid = threadIdx.x;
    int v = (tid < nb) ? bsum[tid] : 0;
    sh[tid] = v;
    __syncthreads();
#pragma unroll
    for (int off = 1; off < 128; off <<= 1) {
        int t = (tid >= off) ? sh[tid - off] : 0;
        __syncthreads();
        sh[tid] += t;
        __syncthreads();
    }
    bscan[tid] = sh[tid] - v;
}
__global__ void scan_fix_kernel(int* rowstart, int* cursor, const int* __restrict__ bscan, int M) {
    int i = blockIdx.x * blockDim.x + threadIdx.x;
    if (i < M) {
        int r = rowstart[i] + bscan[i >> 10];
        rowstart[i] = r;
        cursor[i]   = r;
    }
}
__global__ void csr_fill_kernel(const int* __restrict__ src, const int* __restrict__ dst,
                                int* cursor, int* csr_src, int E) {
    int e = blockIdx.x * blockDim.x + threadIdx.x;
    if (e < E) {
        int d = dst[e];
        int pos = atomicAdd(&cursor[d], 1);
        csr_src[pos] = src[e];
    }
}

// ---------------- bf16 split / mma / cp.async helpers ----------------
// pack two floats into one b32: low 16 bits = bf16(e), high = bf16(o)
__device__ __forceinline__ uint32_t pack_bf16(float e, float o) {
    uint32_t r;
    asm("cvt.rn.bf16x2.f32 %0, %1, %2;" : "=r"(r) : "f"(o), "f"(e));
    return r;
}
// 2-term bf16 split of a float pair: hi holds bf16(e),bf16(o); lo the residuals
__device__ __forceinline__ void split_bf16x2(float e, float o, uint32_t& hi, uint32_t& lo) {
    hi = pack_bf16(e, o);
    float he = __uint_as_float(hi << 16);          // exact bf16 -> f32
    float ho = __uint_as_float(hi & 0xffff0000u);
    lo = pack_bf16(e - he, o - ho);
}
__device__ __forceinline__ void mma_bf16(float* c, const uint32_t* a, const uint32_t* b) {
    asm volatile(
        "mma.sync.aligned.m16n8k16.row.col.f32.bf16.bf16.f32 "
        "{%0,%1,%2,%3}, {%4,%5,%6,%7}, {%8,%9}, {%0,%1,%2,%3};"
        : "+f"(c[0]), "+f"(c[1]), "+f"(c[2]), "+f"(c[3])
        : "r"(a[0]), "r"(a[1]), "r"(a[2]), "r"(a[3]),
          "r"(b[0]), "r"(b[1]));
}
__device__ __forceinline__ void cp_async16(uint32_t saddr, const void* gaddr, bool pred) {
    int sz = pred ? 16 : 0;
    asm volatile("cp.async.cg.shared.global [%0], [%1], 16, %2;"
                 :: "r"(saddr), "l"(gaddr), "r"(sz));
}
__device__ __forceinline__ void cp_commit() {
    asm volatile("cp.async.commit_group;" ::: "memory");
}
template <int NN>
__device__ __forceinline__ void cp_wait() {
    asm volatile("cp.async.wait_group %0;" :: "n"(NN) : "memory");
}

// ---------------- split W into packed bf16 hi/lo: [K/2 x N] ----------------
__global__ void split_w_kernel(const float* __restrict__ W, uint32_t* whi, uint32_t* wlo,
                               int L, int N) {
    int i = blockIdx.x * blockDim.x + threadIdx.x;   // over (K/2)*N
    if (i < L) {
        int kp = i / N, n = i % N;
        float e = W[(2 * kp)     * N + n];
        float o = W[(2 * kp + 1) * N + n];
        split_bf16x2(e, o, whi[i], wlo[i]);
    }
}

// ---------------- tensor-core GEMM (bf16x3, m16n8k16, cp.async pipelined) ----
// hs = f(A) @ W * dinv[row]; if FUSE: f(a) = relu(a*dinv[row] + bprev[k])
// A: [M,128] fp32 row-major. W pre-split packed bf16 hi/lo: [K/2, N].
template <int N, bool FUSE>
__global__ __launch_bounds__(512, 1)
void gemm_mma_kernel(const float* __restrict__ A,
                     const uint32_t* __restrict__ Whi, const uint32_t* __restrict__ Wlo,
                     const float* __restrict__ dinv, const float* __restrict__ bprev,
                     float* __restrict__ hs, int M)
{
    constexpr int BM = 128, K = 128, KC = 16, KP = 8, CHUNKS = K / KC;
    constexpr int SA = KC + 4;                 // 20 floats (A chunk row)
    constexpr int SB = N + 8;                  // 136 / 72 u32 (packed W row)
    constexpr int WN = 32;
    constexpr int WARPSN = N / WN;             // 4 or 2
    constexpr int WM = (N == 128) ? 32 : 16;
    constexpr int FM = WM / 16;                // 2 or 1
    constexpr int FN = 4;

    __shared__ float    As   [2][BM][SA];      // 20.5 KB
    __shared__ uint32_t Bs_hi[2][KP][SB];      // 8.7 / 4.6 KB
    __shared__ uint32_t Bs_lo[2][KP][SB];
    __shared__ float    bs[K];

    const int tid   = threadIdx.x;
    const int lane  = tid & 31;
    const int warp  = tid >> 5;
    const int warpN = warp % WARPSN;
    const int warpM = warp / WARPSN;
    const int row0  = blockIdx.x * BM;
    const int g4    = lane >> 2;
    const int t4    = lane & 3;

    if (FUSE && tid < K) bs[tid] = bprev[tid];

    float acc[FM][FN][4];
#pragma unroll
    for (int i = 0; i < FM; i++)
#pragma unroll
        for (int j = 0; j < FN; j++)
#pragma unroll
            for (int q = 0; q < 4; q++) acc[i][j][q] = 0.f;

    float dv[FM][2];
#pragma unroll
    for (int fm = 0; fm < FM; fm++) {
        int r = row0 + warpM * WM + fm * 16 + g4;
        dv[fm][0] = (r     < M) ? dinv[r]     : 0.f;
        dv[fm][1] = (r + 8 < M) ? dinv[r + 8] : 0.f;
    }

    auto issue = [&](int cc) {
        int k0  = cc * KC;
        int kp0 = cc * KP;
        int buf = cc & 1;
        {   // A: 128x16 fp32 = 512 float4, one per thread
            int r  = tid >> 2;
            int c4 = (tid & 3) * 4;
            bool p = (row0 + r) < M;
            cp_async16((uint32_t)__cvta_generic_to_shared(&As[buf][r][c4]),
                       A + (size_t)(row0 + r) * K + k0 + c4, p);
        }
        if (N == 128) {    // Whi/Wlo: 8x128 u32 = 256 uint4 each
            if (tid < 256) {
                int r = tid >> 5, c = (tid & 31) * 4;
                cp_async16((uint32_t)__cvta_generic_to_shared(&Bs_hi[buf][r][c]),
                           Whi + (size_t)(kp0 + r) * N + c, true);
            } else {
                int t = tid - 256;
                int r = t >> 5, c = (t & 31) * 4;
                cp_async16((uint32_t)__cvta_generic_to_shared(&Bs_lo[buf][r][c]),
                           Wlo + (size_t)(kp0 + r) * N + c, true);
            }
        } else {           // 8x64 u32 = 128 uint4 each
            if (tid < 128) {
                int r = tid >> 4, c = (tid & 15) * 4;
                cp_async16((uint32_t)__cvta_generic_to_shared(&Bs_hi[buf][r][c]),
                           Whi + (size_t)(kp0 + r) * N + c, true);
            } else if (tid < 256) {
                int t = tid - 128;
                int r = t >> 4, c = (t & 15) * 4;
                cp_async16((uint32_t)__cvta_generic_to_shared(&Bs_lo[buf][r][c]),
                           Wlo + (size_t)(kp0 + r) * N + c, true);
            }
        }
        cp_commit();
    };

    issue(0);

    for (int c = 0; c < CHUNKS; c++) {
        if (c + 1 < CHUNKS) { issue(c + 1); cp_wait<1>(); }
        else                { cp_wait<0>(); }
        __syncthreads();

        const int buf = c & 1;
        const int k0  = c * KC;

        // ---- A fragments: fp32 pairs -> (FUSE) -> bf16 hi/lo packed ----
        uint32_t ah[FM][4], al[FM][4];
#pragma unroll
        for (int fm = 0; fm < FM; fm++) {
            int rb = warpM * WM + fm * 16 + g4;
            float2 p00 = *(const float2*)&As[buf][rb    ][2 * t4];
            float2 p10 = *(const float2*)&As[buf][rb + 8][2 * t4];
            float2 p01 = *(const float2*)&As[buf][rb    ][2 * t4 + 8];
            float2 p11 = *(const float2*)&As[buf][rb + 8][2 * t4 + 8];
            if (FUSE) {
                float2 bb0 = *(const float2*)&bs[k0 + 2 * t4];
                float2 bb1 = *(const float2*)&bs[k0 + 2 * t4 + 8];
                p00.x = fmaxf(fmaf(p00.x, dv[fm][0], bb0.x), 0.f);
                p00.y = fmaxf(fmaf(p00.y, dv[fm][0], bb0.y), 0.f);
                p10.x = fmaxf(fmaf(p10.x, dv[fm][1], bb0.x), 0.f);
                p10.y = fmaxf(fmaf(p10.y, dv[fm][1], bb0.y), 0.f);
                p01.x = fmaxf(fmaf(p01.x, dv[fm][0], bb1.x), 0.f);
                p01.y = fmaxf(fmaf(p01.y, dv[fm][0], bb1.y), 0.f);
                p11.x = fmaxf(fmaf(p11.x, dv[fm][1], bb1.x), 0.f);
                p11.y = fmaxf(fmaf(p11.y, dv[fm][1], bb1.y), 0.f);
            }
            split_bf16x2(p00.x, p00.y, ah[fm][0], al[fm][0]);
            split_bf16x2(p10.x, p10.y, ah[fm][1], al[fm][1]);
            split_bf16x2(p01.x, p01.y, ah[fm][2], al[fm][2]);
            split_bf16x2(p11.x, p11.y, ah[fm][3], al[fm][3]);
        }
        // ---- B fragments: packed u32 straight from smem ----
        uint32_t bh[FN][2], bl[FN][2];
#pragma unroll
        for (int fn = 0; fn < FN; fn++) {
            int cn = warpN * WN + fn * 8 + g4;
            bh[fn][0] = Bs_hi[buf][t4    ][cn];
            bh[fn][1] = Bs_hi[buf][t4 + 4][cn];
            bl[fn][0] = Bs_lo[buf][t4    ][cn];
            bl[fn][1] = Bs_lo[buf][t4 + 4][cn];
        }
#pragma unroll
        for (int fm = 0; fm < FM; fm++)
#pragma unroll
            for (int fn = 0; fn < FN; fn++) {
                mma_bf16(acc[fm][fn], ah[fm], bh[fn]);   // hi*hi
                mma_bf16(acc[fm][fn], ah[fm], bl[fn]);   // hi*lo
                mma_bf16(acc[fm][fn], al[fm], bh[fn]);   // lo*hi
            }
        __syncthreads();
    }

    // epilogue: scale by dinv[row], write hs only
#pragma unroll
    for (int fm = 0; fm < FM; fm++) {
        int r_lo = row0 + warpM * WM + fm * 16 + g4;
        int r_hi = r_lo + 8;
        float d0 = dv[fm][0];
        float d1 = dv[fm][1];
#pragma unroll
        for (int fn = 0; fn < FN; fn++) {
            int col = warpN * WN + fn * 8 + t4 * 2;
            if (r_lo < M)
                *(float2*)(hs + (size_t)r_lo * N + col) =
                    make_float2(acc[fm][fn][0] * d0, acc[fm][fn][1] * d0);
            if (r_hi < M)
                *(float2*)(hs + (size_t)r_hi * N + col) =
                    make_float2(acc[fm][fn][2] * d1, acc[fm][fn][3] * d1);
        }
    }
}

// ---------------- CSR aggregate: out[d] = hs[d] + sum_{s in N(d)} hs[s] -------
// FINAL: out[d] = (...)*dinv[d] + bias  (layer 3 writes d_out directly)
template <int N, bool FINAL>
__global__ __launch_bounds__(256)
void aggregate_kernel(const int* __restrict__ csr_src, const int* __restrict__ rowstart,
                      const int* __restrict__ deg, const float* __restrict__ hs,
                      const float* __restrict__ dinv, const float* __restrict__ bias,
                      float* __restrict__ out, int M)
{
    constexpr int CH  = N / 4;               // float4 chunks per row
    constexpr int NPW = 32 / CH;             // nodes per warp: 1 (N=128) / 2 (N=64)
    int warpId = (blockIdx.x * blockDim.x + threadIdx.x) >> 5;
    int lane   = threadIdx.x & 31;
    int g      = lane / CH;
    int j      = lane % CH;
    int node   = warpId * NPW + g;
    if (node >= M) return;

    const float4* hsv = (const float4*)hs;
    float4 acc = __ldg(hsv + (size_t)node * CH + j);     // self-loop term
    int beg = rowstart[node];
    int end = beg + deg[node] - 1;

    int e = beg;
    // 4-wide unroll for memory-level parallelism
    for (; e + 4 <= end; e += 4) {
        int s0 = __ldg(csr_src + e);
        int s1 = __ldg(csr_src + e + 1);
        int s2 = __ldg(csr_src + e + 2);
        int s3 = __ldg(csr_src + e + 3);
        float4 v0 = __ldg(hsv + (size_t)s0 * CH + j);
        float4 v1 = __ldg(hsv + (size_t)s1 * CH + j);
        float4 v2 = __ldg(hsv + (size_t)s2 * CH + j);
        float4 v3 = __ldg(hsv + (size_t)s3 * CH + j);
        acc.x += v0.x; acc.y += v0.y; acc.z += v0.z; acc.w += v0.w;
        acc.x += v1.x; acc.y += v1.y; acc.z += v1.z; acc.w += v1.w;
        acc.x += v2.x; acc.y += v2.y; acc.z += v2.z; acc.w += v2.w;
        acc.x += v3.x; acc.y += v3.y; acc.z += v3.z; acc.w += v3.w;
    }
    for (; e < end; e++) {
        int s = __ldg(csr_src + e);
        float4 v = __ldg(hsv + (size_t)s * CH + j);
        acc.x += v.x; acc.y += v.y; acc.z += v.z; acc.w += v.w;
    }
    if (FINAL) {
        float di = dinv[node];
        float4 bb = __ldg((const float4*)bias + j);
        acc.x = fmaf(acc.x, di, bb.x);
        acc.y = fmaf(acc.y, di, bb.y);
        acc.z = fmaf(acc.z, di, bb.z);
        acc.w = fmaf(acc.w, di, bb.w);
    }
    ((float4*)out)[(size_t)node * CH + j] = acc;
}

// ---------------- launch ----------------
extern "C" void kernel_launch(void* const* d_in, const int* in_sizes, int n_in,
                              void* d_out, int out_size)
{
    const float* x  = (const float*)d_in[0];
    const int*   ei = (const int*)  d_in[1];
    const float* W1 = (const float*)d_in[2];
    const float* b1 = (const float*)d_in[3];
    const float* W2 = (const float*)d_in[4];
    const float* b2 = (const float*)d_in[5];
    const float* W3 = (const float*)d_in[6];
    const float* b3 = (const float*)d_in[7];

    const int M = in_sizes[0] / FEAT;     // 100000
    const int E = in_sizes[1] / 2;        // 800000
    const int* src = ei;
    const int* dst = ei + E;

    float *hs, *agg, *dinv; int *deg, *rowstart, *cursor, *csr_src, *bsum, *bscan;
    uint32_t *whi, *wlo;
    cudaGetSymbolAddress((void**)&hs,       g_hs);
    cudaGetSymbolAddress((void**)&agg,      g_agg);
    cudaGetSymbolAddress((void**)&dinv,     g_dinv);
    cudaGetSymbolAddress((void**)&deg,      g_deg);
    cudaGetSymbolAddress((void**)&rowstart, g_rowstart);
    cudaGetSymbolAddress((void**)&cursor,   g_cursor);
    cudaGetSymbolAddress((void**)&csr_src,  g_csr_src);
    cudaGetSymbolAddress((void**)&bsum,     g_bsum);
    cudaGetSymbolAddress((void**)&bscan,    g_bscan);
    cudaGetSymbolAddress((void**)&whi,      g_whi);
    cudaGetSymbolAddress((void**)&wlo,      g_wlo);

    // degrees + dinv
    deg_init_kernel<<<(M + 255) / 256, 256>>>(deg, M);
    deg_acc_kernel <<<(E + 255) / 256, 256>>>(deg, dst, E);
    dinv_kernel    <<<(M + 255) / 256, 256>>>(dinv, deg, M);

    // CSR build (by dst)
    int nb = (M + 1023) / 1024;
    scan_block_kernel<<<nb, 1024>>>(deg, rowstart, bsum, M);
    scan_tops_kernel <<<1, 128>>>(bsum, bscan, nb);
    scan_fix_kernel  <<<(M + 255) / 256, 256>>>(rowstart, cursor, bscan, M);
    csr_fill_kernel  <<<(E + 255) / 256, 256>>>(src, dst, cursor, csr_src, E);

    // pre-split weights into packed bf16 hi/lo
    split_w_kernel<<<(8192 + 255) / 256, 256>>>(W1, whi,         wlo,         8192, 128);
    split_w_kernel<<<(8192 + 255) / 256, 256>>>(W2, whi + 8192,  wlo + 8192,  8192, 128);
    split_w_kernel<<<(4096 + 255) / 256, 256>>>(W3, whi + 16384, wlo + 16384, 4096,  64);

    const int gemm_blocks = (M + 127) / 128;
    const int agg_blocks_128 = (M * 32 + 255) / 256;         // 1 node / warp
    const int agg_blocks_64  = (M * 16 + 255) / 256;         // 2 nodes / warp

    // ---- layer 1: 128 -> 128 ----
    gemm_mma_kernel<128, false><<<gemm_blocks, 512>>>(x, whi, wlo, dinv, nullptr, hs, M);
    aggregate_kernel<128, false><<<agg_blocks_128, 256>>>(csr_src, rowstart, deg, hs, dinv, nullptr, agg, M);

    // ---- layer 2: 128 -> 128 (layer-1 finalize fused into A path) ----
    gemm_mma_kernel<128, true><<<gemm_blocks, 512>>>(agg, whi + 8192, wlo + 8192, dinv, b1, hs, M);
    aggregate_kernel<128, false><<<agg_blocks_128, 256>>>(csr_src, rowstart, deg, hs, dinv, nullptr, agg, M);

    // ---- layer 3: 128 -> 64 (layer-2 finalize fused); final aggregate writes d_out ----
    gemm_mma_kernel<64, true><<<gemm_blocks, 512>>>(agg, whi + 16384, wlo + 16384, dinv, b2, hs, M);
    aggregate_kernel<64, true><<<agg_blocks_64, 256>>>(csr_src, rowstart, deg, hs, dinv, b3, (float*)d_out, M);
}